// round 14
// baseline (speedup 1.0000x reference)
#include <cuda_runtime.h>
#include <math.h>

#define BB  8
#define NPT 2048
#define NTOT (BB*NPT)
#define HID 256
#define NITER 14

typedef unsigned long long u64;

// ---------------- f32x2 packed helpers (sm_103a) ----------------
__device__ __forceinline__ u64 pk2(float lo, float hi) {
    u64 r; asm("mov.b64 %0,{%1,%2};" : "=l"(r) : "f"(lo), "f"(hi)); return r;
}
__device__ __forceinline__ void up2(u64 v, float& lo, float& hi) {
    asm("mov.b64 {%0,%1},%2;" : "=f"(lo), "=f"(hi) : "l"(v));
}
__device__ __forceinline__ u64 fma2_(u64 a, u64 b, u64 c) {
    u64 r; asm("fma.rn.f32x2 %0,%1,%2,%3;" : "=l"(r) : "l"(a), "l"(b), "l"(c)); return r;
}
__device__ __forceinline__ float ex2_(float x) {
    float r; asm("ex2.approx.f32 %0,%1;" : "=f"(r) : "f"(x)); return r;
}

// ---------------- persistent scratch ----------------
__device__ float4 g_xp[NTOT];   // noise points packed: (x,y,z,|x|^2)
__device__ float4 g_yp[NTOT];   // x0 points packed:    (x,y,z,|y|^2)
// interleaved pair tiles for the sinkhorn reduce side:
//   g_xy*[pair] = (x_{2j}, x_{2j+1}, y_{2j}, y_{2j+1})
//   g_zc*[pair] = (z_{2j}, z_{2j+1}, c_{2j}, c_{2j+1}),  c = phi - 0.5*|p|^2
__device__ float4 g_xyX[NTOT/2], g_zcX[NTOT/2];   // X side (noise)
__device__ float4 g_xyY[NTOT/2], g_zcY[NTOT/2];   // Y side (x0)
__device__ float  g_g[NTOT];
__device__ float  g_std[BB];
__device__ int    g_idx[NTOT];
__device__ int    g_cnt[BB];       // per-batch phase arrival counter (zeroed by k_pack each launch)

// ---------------- per-batch std (ddof=1) ----------------
__global__ void k_std(const float* __restrict__ cloud) {
    __shared__ float red[256];
    const int b = blockIdx.x;
    const float* p = cloud + b * NPT * 3;
    const int tid = threadIdx.x;
    float s = 0.f;
    for (int i = tid; i < NPT * 3; i += 256) s += p[i];
    red[tid] = s; __syncthreads();
    for (int o = 128; o > 0; o >>= 1) { if (tid < o) red[tid] += red[tid + o]; __syncthreads(); }
    const float mean = red[0] / (float)(NPT * 3);
    __syncthreads();
    float s2 = 0.f;
    for (int i = tid; i < NPT * 3; i += 256) { float d = p[i] - mean; s2 = fmaf(d, d, s2); }
    red[tid] = s2; __syncthreads();
    for (int o = 128; o > 0; o >>= 1) { if (tid < o) red[tid] += red[tid + o]; __syncthreads(); }
    if (tid == 0) g_std[b] = sqrtf(red[0] / (float)(NPT * 3 - 1));
}

// ---------------- pack points, build interleaved tiles, init folded constants ----------------
__global__ void k_pack(const float* __restrict__ cloud, const float* __restrict__ noise) {
    int i = blockIdx.x * blockDim.x + threadIdx.x;
    if (i >= NTOT) return;
    int b = i >> 11;
    float sd = g_std[b];
    float c0 = cloud[i * 3 + 0] / sd;
    float c1 = cloud[i * 3 + 1] / sd;
    float c2 = cloud[i * 3 + 2] / sd;
    float yn = __fadd_rn(__fadd_rn(__fmul_rn(c0, c0), __fmul_rn(c1, c1)), __fmul_rn(c2, c2));
    g_yp[i] = make_float4(c0, c1, c2, yn);
    float n0 = noise[i * 3 + 0], n1 = noise[i * 3 + 1], n2 = noise[i * 3 + 2];
    float xn = __fadd_rn(__fadd_rn(__fmul_rn(n0, n0), __fmul_rn(n1, n1)), __fmul_rn(n2, n2));
    g_xp[i] = make_float4(n0, n1, n2, xn);

    const int pr = i >> 1, h = i & 1;
    float* fxyX = (float*)g_xyX; float* fzcX = (float*)g_zcX;
    float* fxyY = (float*)g_xyY; float* fzcY = (float*)g_zcY;
    fxyX[pr * 4 + h]     = n0;
    fxyX[pr * 4 + 2 + h] = n1;
    fzcX[pr * 4 + h]     = n2;
    fzcX[pr * 4 + 2 + h] = __fmul_rn(-0.5f, xn);   // phi==0 -> c = -0.5|x|^2
    fxyY[pr * 4 + h]     = c0;
    fxyY[pr * 4 + 2 + h] = c1;
    fzcY[pr * 4 + h]     = c2;
    fzcY[pr * 4 + 2 + h] = __fmul_rn(-0.5f, yn);

    if (i < BB) g_cnt[i] = 0;
}

// log2(1/2048) is exactly -11
#define LOGC2 (-11.0f)
#define LN2F  (0.6931471805599453f)

struct EpsTab { float eps[NITER]; float ie2[NITER]; };

// ---------------- persistent Sinkhorn: all 28 half-updates in ONE kernel ----------------
// Inner loop identical to the R9 best (single pass, duality shift khat = c_row*ie2; duality
// bounds the max exp2 arg <= ~96 < fp32 overflow 117, tails underflow ex2 to 0).
// Grid (64, 8): block owns 32 rows of its batch for all phases. Between phases: per-batch
// arrive-and-spin barrier on a monotonic counter (release: per-thread threadfence before
// leader's atomicAdd; acquire: leader fence after spin + syncthreads). All 512 blocks are
// co-resident by construction (launch_bounds(256,5) -> 740 >= 512), so spinning cannot deadlock.
// Cross-block data (c channel, crow) is read with __ldcg (L2) since L1 is incoherent and not
// flushed within the launch; static coords/q stay L1-cacheable and become L1-hot across phases.
__global__ void __launch_bounds__(256, 5) k_sink(EpsTab T) {
    __shared__ __align__(16) ulonglong2 sXY[NPT/2], sZC[NPT/2];
    const int b = blockIdx.y;
    const int base = b * NPT;
    const int rowblock = blockIdx.x;
    const int tid = threadIdx.x;
    const int warp = tid >> 5, lane = tid & 31;
    const int r0 = rowblock * 32 + warp * 4;

    for (int ph = 0; ph < 2 * NITER; ++ph) {
        const int DIR = ph & 1;
        const float eps = T.eps[ph >> 1];
        const float ie2 = T.ie2[ph >> 1];
        const float4* __restrict__ vxy = (DIR ? g_xyX : g_xyY) + (base >> 1);
        const float4* __restrict__ vzc = (DIR ? g_zcX : g_zcY) + (base >> 1);
        const float4* __restrict__ Pq  = DIR ? g_yp : g_xp;
        const float*  __restrict__ rowzc = (const float*)(DIR ? g_zcY : g_zcX);

        {
            float4* dxy = (float4*)sXY; float4* dzc = (float4*)sZC;
#pragma unroll
            for (int j = tid; j < NPT / 2; j += 256) {
                dxy[j] = vxy[j];            // coords only: L1-cacheable, hot across phases
                dzc[j] = __ldcg(vzc + j);   // carries c: must come from L2
            }
        }
        __syncthreads();

        u64 qx2[4], qy2[4], qz2[4], K[4];
        float qw[4];
#pragma unroll
        for (int k = 0; k < 4; k++) {
            float4 q = Pq[base + r0 + k];
            qx2[k] = pk2(q.x, q.x);
            qy2[k] = pk2(q.y, q.y);
            qz2[k] = pk2(q.z, q.z);
            qw[k] = q.w;
            float crow = __ldcg(rowzc + (((base + r0) >> 1) + (k >> 1)) * 4 + 2 + (k & 1));
            float khat = __fmul_rn(crow, ie2);
            K[k] = pk2(khat, khat);
        }
        const u64 IE2P = pk2(ie2, ie2);

        float aL[4] = {0.f, 0.f, 0.f, 0.f};
        float aH[4] = {0.f, 0.f, 0.f, 0.f};

#pragma unroll 4
        for (int it = 0; it < NPT / 64; ++it) {
            const int jj = lane + it * 32;
            const ulonglong2 pxy = sXY[jj];
            const ulonglong2 pzc = sZC[jj];
#pragma unroll
            for (int k = 0; k < 4; k++) {
                u64 t  = fma2_(qz2[k], pzc.x, fma2_(qy2[k], pxy.y, fma2_(qx2[k], pxy.x, pzc.y)));
                u64 ea = fma2_(IE2P, t, K[k]);
                float el, eh; up2(ea, el, eh);
                aL[k] += ex2_(el);
                aH[k] += ex2_(eh);
            }
        }

#pragma unroll
        for (int k = 0; k < 4; k++) {
            float a = __fadd_rn(aL[k], aH[k]);
#pragma unroll
            for (int o = 16; o; o >>= 1) a += __shfl_xor_sync(0xffffffffu, a, o);
            aL[k] = a;
        }

        if (lane == 0) {
#pragma unroll
            for (int k = 0; k < 4; k++) {
                const int row = base + r0 + k;
                const int pr4 = (row >> 1) * 4 + 2 + (row & 1);
                float crow = __ldcg(rowzc + pr4);
                float khat = __fmul_rn(crow, ie2);
                float base2 = __fadd_rn(LOGC2, -khat);
                float cnew = __fmul_rn(-eps, fmaf(base2, LN2F, logf(aL[k])));
                if (DIR == 0) {
                    ((float*)g_zcX)[pr4] = cnew;                 // f - 0.5|x|^2
                } else {
                    g_g[row] = fmaf(0.5f, qw[k], cnew);          // g (for argmin)
                    ((float*)g_zcY)[pr4] = cnew;                 // g - 0.5|y|^2
                }
            }
        }

        // ---- per-batch phase barrier (skip after the last phase) ----
        if (ph < 2 * NITER - 1) {
            __threadfence();        // release: every thread's global writes visible
            __syncthreads();        // all threads of this block have fenced
            if (tid == 0) {
                atomicAdd(&g_cnt[b], 1);
                const int target = 64 * (ph + 1);
                while (*((volatile int*)&g_cnt[b]) < target) __nanosleep(64);
                __threadfence();    // acquire
            }
            __syncthreads();
        }
    }
}

// ---------------- argmin over m of (sqdist - g_m), first-index ties ----------------
__global__ void __launch_bounds__(256) k_argmin() {
    __shared__ float4 sp[NPT];
    __shared__ float  sg[NPT];
    const int b = blockIdx.y;
    const int base = b * NPT;
    const int tid = threadIdx.x;
    for (int j = tid; j < NPT; j += 256) { sp[j] = g_yp[base + j]; sg[j] = g_g[base + j]; }
    __syncthreads();
    const int warp = tid >> 5, lane = tid & 31;
    const int r0 = blockIdx.x * 32 + warp * 4;

    float qx[4], qy[4], qz[4], qn[4];
#pragma unroll
    for (int k = 0; k < 4; k++) {
        float4 q = g_xp[base + r0 + k];
        qx[k] = q.x; qy[k] = q.y; qz[k] = q.z; qn[k] = q.w;
    }
    float bv[4] = {INFINITY, INFINITY, INFINITY, INFINITY};
    int   bi[4] = {0, 0, 0, 0};
#pragma unroll 2
    for (int j = lane; j < NPT; j += 32) {
        const float4 p = sp[j];
        const float gg = sg[j];
#pragma unroll
        for (int k = 0; k < 4; k++) {
            float d = fmaf(qz[k], p.z, fmaf(qy[k], p.y, __fmul_rn(qx[k], p.x)));
            float s = fmaf(-2.f, d, __fadd_rn(qn[k], p.w));
            s = fmaxf(s, 0.f);
            float v = __fadd_rn(s, -gg);
            if (v < bv[k]) { bv[k] = v; bi[k] = j; }
        }
    }
#pragma unroll
    for (int k = 0; k < 4; k++) {
#pragma unroll
        for (int o = 16; o; o >>= 1) {
            float v2 = __shfl_xor_sync(0xffffffffu, bv[k], o);
            int   i2 = __shfl_xor_sync(0xffffffffu, bi[k], o);
            if (v2 < bv[k] || (v2 == bv[k] && i2 < bi[k])) { bv[k] = v2; bi[k] = i2; }
        }
    }
    if (lane == 0) {
#pragma unroll
        for (int k = 0; k < 4; k++) g_idx[base + r0 + k] = bi[k];
    }
}

// ---------------- gather + MLP head, write (v_pred, v) ----------------
__global__ void __launch_bounds__(256) k_mlp(const float* __restrict__ noise, const float* __restrict__ tt,
                                             const float* __restrict__ W1, const float* __restrict__ Wt,
                                             const float* __restrict__ b1, const float* __restrict__ W2,
                                             const float* __restrict__ b2, float* __restrict__ out) {
    __shared__ float sW1[3 * HID], sW2[HID * 3], sWt[HID], sb1[HID];
    const int tid = threadIdx.x;
    for (int i = tid; i < 3 * HID; i += 256) { sW1[i] = W1[i]; sW2[i] = W2[i]; }
    for (int i = tid; i < HID; i += 256) { sWt[i] = Wt[i]; sb1[i] = b1[i]; }
    __syncthreads();

    const int p = blockIdx.x * 256 + tid;
    const int b = p >> 11;
    const float t = tt[b];
    const int id = g_idx[p];
    const float4 y = g_yp[(b << 11) + id];
    const float n0 = noise[p * 3 + 0], n1 = noise[p * 3 + 1], n2 = noise[p * 3 + 2];
    const float v0 = __fadd_rn(n0, -y.x);
    const float v1 = __fadd_rn(n1, -y.y);
    const float v2 = __fadd_rn(n2, -y.z);
    const float omt = __fadd_rn(1.f, -t);
    const float x0t = __fadd_rn(__fmul_rn(omt, y.x), __fmul_rn(t, n0));
    const float x1t = __fadd_rn(__fmul_rn(omt, y.y), __fmul_rn(t, n1));
    const float x2t = __fadd_rn(__fmul_rn(omt, y.z), __fmul_rn(t, n2));

    float a0 = b2[0], a1 = b2[1], a2 = b2[2];
#pragma unroll 8
    for (int j = 0; j < HID; j++) {
        float h = fmaf(x2t, sW1[2 * HID + j], fmaf(x1t, sW1[HID + j], __fmul_rn(x0t, sW1[j])));
        h = __fadd_rn(__fadd_rn(h, __fmul_rn(t, sWt[j])), sb1[j]);
        h = fmaxf(h, 0.f);
        a0 = fmaf(h, sW2[j * 3 + 0], a0);
        a1 = fmaf(h, sW2[j * 3 + 1], a1);
        a2 = fmaf(h, sW2[j * 3 + 2], a2);
    }
    out[p * 3 + 0] = a0;
    out[p * 3 + 1] = a1;
    out[p * 3 + 2] = a2;
    out[NTOT * 3 + p * 3 + 0] = v0;
    out[NTOT * 3 + p * 3 + 1] = v1;
    out[NTOT * 3 + p * 3 + 2] = v2;
}

// ---------------- launcher ----------------
extern "C" void kernel_launch(void* const* d_in, const int* in_sizes, int n_in,
                              void* d_out, int out_size) {
    const float* cloud = (const float*)d_in[0];
    const float* noise = (const float*)d_in[1];
    const float* t     = (const float*)d_in[2];
    const float* W1    = (const float*)d_in[3];
    const float* Wt    = (const float*)d_in[4];
    const float* b1    = (const float*)d_in[5];
    const float* W2    = (const float*)d_in[6];
    const float* b2    = (const float*)d_in[7];
    float* out = (float*)d_out;

    k_std<<<BB, 256>>>(cloud);
    k_pack<<<NTOT / 256, 256>>>(cloud, noise);

    // EPS_LIST = np.geomspace(32.0, 0.001**2, 14).astype(np.float32) — same values as before
    EpsTab T;
    {
        const double blur2 = 0.001 * 0.001;
        const double l0 = log10(32.0);
        const double l1 = log10(blur2);
        const double step = (l1 - l0) / (double)(NITER - 1);
        const double LOG2E = 1.4426950408889634;
        for (int it = 0; it < NITER; it++) {
            double ev;
            if (it == 0)              ev = 32.0;
            else if (it == NITER - 1) ev = blur2;
            else                      ev = pow(10.0, l0 + (double)it * step);
            T.eps[it] = (float)ev;
            T.ie2[it] = (float)((double)(1.0f / T.eps[it]) * LOG2E);
        }
    }

    k_sink<<<dim3(NPT / 32, BB), 256>>>(T);   // 512 blocks, all co-resident

    k_argmin<<<dim3(NPT / 32, BB), 256>>>();
    k_mlp<<<NTOT / 256, 256>>>(noise, t, W1, Wt, b1, W2, b2, out);

    (void)in_sizes; (void)n_in; (void)out_size;
}

// round 15
// speedup vs baseline: 1.3826x; 1.3826x over previous
#include <cuda_runtime.h>
#include <math.h>

#define BB  8
#define NPT 2048
#define NTOT (BB*NPT)
#define HID 256
#define NITER 14

typedef unsigned long long u64;

// ---------------- f32x2 packed helpers (sm_103a) ----------------
__device__ __forceinline__ u64 pk2(float lo, float hi) {
    u64 r; asm("mov.b64 %0,{%1,%2};" : "=l"(r) : "f"(lo), "f"(hi)); return r;
}
__device__ __forceinline__ void up2(u64 v, float& lo, float& hi) {
    asm("mov.b64 {%0,%1},%2;" : "=f"(lo), "=f"(hi) : "l"(v));
}
__device__ __forceinline__ u64 fma2_(u64 a, u64 b, u64 c) {
    u64 r; asm("fma.rn.f32x2 %0,%1,%2,%3;" : "=l"(r) : "l"(a), "l"(b), "l"(c)); return r;
}
__device__ __forceinline__ float ex2_(float x) {
    float r; asm("ex2.approx.f32 %0,%1;" : "=f"(r) : "f"(x)); return r;
}

// ---------------- persistent scratch ----------------
__device__ float4 g_xp[NTOT];   // noise points packed: (x,y,z,|x|^2)
__device__ float4 g_yp[NTOT];   // x0 points packed:    (x,y,z,|y|^2)
// interleaved pair tiles for k_half / k_argmin reduce side:
//   g_xy*[pair] = (x_{2j}, x_{2j+1}, y_{2j}, y_{2j+1})
//   g_zc*[pair] = (z_{2j}, z_{2j+1}, c_{2j}, c_{2j+1}),  c = phi - 0.5*|p|^2
//   (after the LAST g-update, the c channel of g_zcY holds cg = 0.5*g - 0.5*|y|^2)
__device__ float4 g_xyX[NTOT/2], g_zcX[NTOT/2];   // X side (noise)
__device__ float4 g_xyY[NTOT/2], g_zcY[NTOT/2];   // Y side (x0)
__device__ float  g_std[BB];
__device__ int    g_idx[NTOT];

// ---------------- per-batch std (ddof=1) ----------------
__global__ void k_std(const float* __restrict__ cloud) {
    __shared__ float red[256];
    const int b = blockIdx.x;
    const float* p = cloud + b * NPT * 3;
    const int tid = threadIdx.x;
    float s = 0.f;
    for (int i = tid; i < NPT * 3; i += 256) s += p[i];
    red[tid] = s; __syncthreads();
    for (int o = 128; o > 0; o >>= 1) { if (tid < o) red[tid] += red[tid + o]; __syncthreads(); }
    const float mean = red[0] / (float)(NPT * 3);
    __syncthreads();
    float s2 = 0.f;
    for (int i = tid; i < NPT * 3; i += 256) { float d = p[i] - mean; s2 = fmaf(d, d, s2); }
    red[tid] = s2; __syncthreads();
    for (int o = 128; o > 0; o >>= 1) { if (tid < o) red[tid] += red[tid + o]; __syncthreads(); }
    if (tid == 0) g_std[b] = sqrtf(red[0] / (float)(NPT * 3 - 1));
}

// ---------------- pack points, build interleaved tiles, init folded constants ----------------
__global__ void k_pack(const float* __restrict__ cloud, const float* __restrict__ noise) {
    int i = blockIdx.x * blockDim.x + threadIdx.x;
    if (i >= NTOT) return;
    int b = i >> 11;
    float sd = g_std[b];
    float c0 = cloud[i * 3 + 0] / sd;
    float c1 = cloud[i * 3 + 1] / sd;
    float c2 = cloud[i * 3 + 2] / sd;
    float yn = __fadd_rn(__fadd_rn(__fmul_rn(c0, c0), __fmul_rn(c1, c1)), __fmul_rn(c2, c2));
    g_yp[i] = make_float4(c0, c1, c2, yn);
    float n0 = noise[i * 3 + 0], n1 = noise[i * 3 + 1], n2 = noise[i * 3 + 2];
    float xn = __fadd_rn(__fadd_rn(__fmul_rn(n0, n0), __fmul_rn(n1, n1)), __fmul_rn(n2, n2));
    g_xp[i] = make_float4(n0, n1, n2, xn);

    const int pr = i >> 1, h = i & 1;
    float* fxyX = (float*)g_xyX; float* fzcX = (float*)g_zcX;
    float* fxyY = (float*)g_xyY; float* fzcY = (float*)g_zcY;
    fxyX[pr * 4 + h]     = n0;
    fxyX[pr * 4 + 2 + h] = n1;
    fzcX[pr * 4 + h]     = n2;
    fzcX[pr * 4 + 2 + h] = __fmul_rn(-0.5f, xn);   // phi==0 -> c = -0.5|x|^2
    fxyY[pr * 4 + h]     = c0;
    fxyY[pr * 4 + 2 + h] = c1;
    fzcY[pr * 4 + h]     = c2;
    fzcY[pr * 4 + 2 + h] = __fmul_rn(-0.5f, yn);
}

// log2(1/2048) is exactly -11
#define LOGC2 (-11.0f)
#define LN2F  (0.6931471805599453f)

// ---------------- one Sinkhorn half-update: single pass, duality-based shift (R9 config) ----------
// arg(i,j) = (q_i.p_j + c_j)*ie2 + khat_i,  khat_i = c_row_i*ie2. Duality bounds the MAX arg
// (<= ~96 < fp32 overflow 117), so no max pass is needed; tails underflow ex2 to 0 harmlessly.
// DIR==0: rows = noise(x), tile = x0(y) -> writes cX.
// DIR==1: rows = x0(y), tile = noise(x) -> writes cY; if LAST, writes cg = 0.5*g - 0.5*|y|^2
//         into the (now dead) c channel for the folded argmin.
template <int DIR, int LAST>
__global__ void __launch_bounds__(256, 4) k_half(float eps, float ie2 /* (1/eps)*log2(e) */) {
    __shared__ __align__(16) ulonglong2 sXY[NPT/2], sZC[NPT/2];
    const int b = blockIdx.y;
    const int base = b * NPT;
    const float4* __restrict__ vxy = (DIR ? g_xyX : g_xyY) + (base >> 1);
    const float4* __restrict__ vzc = (DIR ? g_zcX : g_zcY) + (base >> 1);
    const float4* __restrict__ Pq  = DIR ? g_yp : g_xp;
    const float*  __restrict__ rowzc = (const float*)(DIR ? g_zcY : g_zcX);

    const int tid = threadIdx.x;
    {
        float4* dxy = (float4*)sXY; float4* dzc = (float4*)sZC;
#pragma unroll
        for (int j = tid; j < NPT / 2; j += 256) { dxy[j] = vxy[j]; dzc[j] = vzc[j]; }
    }
    __syncthreads();

    const int warp = tid >> 5, lane = tid & 31;
    const int r0 = blockIdx.x * 32 + warp * 4;

    u64 qx2[4], qy2[4], qz2[4], K[4];
    float qw[4], khat[4];
#pragma unroll
    for (int k = 0; k < 4; k++) {
        float4 q = Pq[base + r0 + k];
        qx2[k] = pk2(q.x, q.x);
        qy2[k] = pk2(q.y, q.y);
        qz2[k] = pk2(q.z, q.z);
        qw[k] = q.w;
        float crow = rowzc[(((base + r0) >> 1) + (k >> 1)) * 4 + 2 + (k & 1)];
        khat[k] = __fmul_rn(crow, ie2);
        K[k] = pk2(khat[k], khat[k]);
    }
    const u64 IE2P = pk2(ie2, ie2);

    float aL[4] = {0.f, 0.f, 0.f, 0.f};
    float aH[4] = {0.f, 0.f, 0.f, 0.f};

#pragma unroll 4
    for (int it = 0; it < NPT / 64; ++it) {
        const int jj = lane + it * 32;
        const ulonglong2 pxy = sXY[jj];
        const ulonglong2 pzc = sZC[jj];
#pragma unroll
        for (int k = 0; k < 4; k++) {
            u64 t  = fma2_(qz2[k], pzc.x, fma2_(qy2[k], pxy.y, fma2_(qx2[k], pxy.x, pzc.y)));
            u64 ea = fma2_(IE2P, t, K[k]);
            float el, eh; up2(ea, el, eh);
            aL[k] += ex2_(el);
            aH[k] += ex2_(eh);
        }
    }

    float sw[4];
#pragma unroll
    for (int k = 0; k < 4; k++) {
        float a = __fadd_rn(aL[k], aH[k]);
#pragma unroll
        for (int o = 16; o; o >>= 1) a += __shfl_xor_sync(0xffffffffu, a, o);
        sw[k] = a;
    }

    if (lane == 0) {
#pragma unroll
        for (int k = 0; k < 4; k++) {
            // cnew = phi_new - 0.5|q|^2 = -eps*( (LOGC2 - khat)*ln2 + ln S )
            float base2 = __fadd_rn(LOGC2, -khat[k]);
            float cnew = __fmul_rn(-eps, fmaf(base2, LN2F, logf(sw[k])));
            const int pr4 = (((base + r0) >> 1) + (k >> 1)) * 4 + 2 + (k & 1);
            if (DIR == 0) {
                ((float*)g_zcX)[pr4] = cnew;                    // f - 0.5|x|^2
            } else if (!LAST) {
                ((float*)g_zcY)[pr4] = cnew;                    // g - 0.5|y|^2
            } else {
                float res = fmaf(0.5f, qw[k], cnew);            // g
                ((float*)g_zcY)[pr4] = fmaf(-0.5f, res, cnew);  // cg = 0.5*g - 0.5*|y|^2
            }
        }
    }
}

// ---------------- folded argmin: argmax_j of u = q.p_j + cg_j (== argmin of sqdist - g) --------
// s - g = |q|^2 - 2*u exactly, so argmin(C - g) == argmax(u); strict '>' keeps the first index.
// Reuses k_half's pair-interleaved Y tiles (c channel now holds cg).
__global__ void __launch_bounds__(256, 4) k_argmin() {
    __shared__ __align__(16) ulonglong2 sXY[NPT/2], sZC[NPT/2];
    const int b = blockIdx.y;
    const int base = b * NPT;
    const int tid = threadIdx.x;
    {
        const float4* vxy = g_xyY + (base >> 1);
        const float4* vzc = g_zcY + (base >> 1);
        float4* dxy = (float4*)sXY; float4* dzc = (float4*)sZC;
#pragma unroll
        for (int j = tid; j < NPT / 2; j += 256) { dxy[j] = vxy[j]; dzc[j] = vzc[j]; }
    }
    __syncthreads();

    const int warp = tid >> 5, lane = tid & 31;
    const int r0 = blockIdx.x * 32 + warp * 4;

    u64 qx2[4], qy2[4], qz2[4];
#pragma unroll
    for (int k = 0; k < 4; k++) {
        float4 q = g_xp[base + r0 + k];
        qx2[k] = pk2(q.x, q.x);
        qy2[k] = pk2(q.y, q.y);
        qz2[k] = pk2(q.z, q.z);
    }
    float bv[4] = {-INFINITY, -INFINITY, -INFINITY, -INFINITY};
    int   bi[4] = {0, 0, 0, 0};

#pragma unroll 4
    for (int it = 0; it < NPT / 64; ++it) {
        const int jj = lane + it * 32;
        const ulonglong2 pxy = sXY[jj];
        const ulonglong2 pzc = sZC[jj];
#pragma unroll
        for (int k = 0; k < 4; k++) {
            u64 u = fma2_(qz2[k], pzc.x, fma2_(qy2[k], pxy.y, fma2_(qx2[k], pxy.x, pzc.y)));
            float ul, uh; up2(u, ul, uh);
            if (ul > bv[k]) { bv[k] = ul; bi[k] = 2 * jj; }
            if (uh > bv[k]) { bv[k] = uh; bi[k] = 2 * jj + 1; }
        }
    }
#pragma unroll
    for (int k = 0; k < 4; k++) {
#pragma unroll
        for (int o = 16; o; o >>= 1) {
            float v2 = __shfl_xor_sync(0xffffffffu, bv[k], o);
            int   i2 = __shfl_xor_sync(0xffffffffu, bi[k], o);
            if (v2 > bv[k] || (v2 == bv[k] && i2 < bi[k])) { bv[k] = v2; bi[k] = i2; }
        }
    }
    if (lane == 0) {
#pragma unroll
        for (int k = 0; k < 4; k++) g_idx[base + r0 + k] = bi[k];
    }
}

// ---------------- gather + MLP head, write (v_pred, v) ----------------
__global__ void __launch_bounds__(256) k_mlp(const float* __restrict__ noise, const float* __restrict__ tt,
                                             const float* __restrict__ W1, const float* __restrict__ Wt,
                                             const float* __restrict__ b1, const float* __restrict__ W2,
                                             const float* __restrict__ b2, float* __restrict__ out) {
    __shared__ float sW1[3 * HID], sW2[HID * 3], sWt[HID], sb1[HID];
    const int tid = threadIdx.x;
    for (int i = tid; i < 3 * HID; i += 256) { sW1[i] = W1[i]; sW2[i] = W2[i]; }
    for (int i = tid; i < HID; i += 256) { sWt[i] = Wt[i]; sb1[i] = b1[i]; }
    __syncthreads();

    const int p = blockIdx.x * 256 + tid;
    const int b = p >> 11;
    const float t = tt[b];
    const int id = g_idx[p];
    const float4 y = g_yp[(b << 11) + id];
    const float n0 = noise[p * 3 + 0], n1 = noise[p * 3 + 1], n2 = noise[p * 3 + 2];
    const float v0 = __fadd_rn(n0, -y.x);
    const float v1 = __fadd_rn(n1, -y.y);
    const float v2 = __fadd_rn(n2, -y.z);
    const float omt = __fadd_rn(1.f, -t);
    const float x0t = __fadd_rn(__fmul_rn(omt, y.x), __fmul_rn(t, n0));
    const float x1t = __fadd_rn(__fmul_rn(omt, y.y), __fmul_rn(t, n1));
    const float x2t = __fadd_rn(__fmul_rn(omt, y.z), __fmul_rn(t, n2));

    float a0 = b2[0], a1 = b2[1], a2 = b2[2];
#pragma unroll 8
    for (int j = 0; j < HID; j++) {
        float h = fmaf(x2t, sW1[2 * HID + j], fmaf(x1t, sW1[HID + j], __fmul_rn(x0t, sW1[j])));
        h = __fadd_rn(__fadd_rn(h, __fmul_rn(t, sWt[j])), sb1[j]);
        h = fmaxf(h, 0.f);
        a0 = fmaf(h, sW2[j * 3 + 0], a0);
        a1 = fmaf(h, sW2[j * 3 + 1], a1);
        a2 = fmaf(h, sW2[j * 3 + 2], a2);
    }
    out[p * 3 + 0] = a0;
    out[p * 3 + 1] = a1;
    out[p * 3 + 2] = a2;
    out[NTOT * 3 + p * 3 + 0] = v0;
    out[NTOT * 3 + p * 3 + 1] = v1;
    out[NTOT * 3 + p * 3 + 2] = v2;
}

// ---------------- launcher ----------------
extern "C" void kernel_launch(void* const* d_in, const int* in_sizes, int n_in,
                              void* d_out, int out_size) {
    const float* cloud = (const float*)d_in[0];
    const float* noise = (const float*)d_in[1];
    const float* t     = (const float*)d_in[2];
    const float* W1    = (const float*)d_in[3];
    const float* Wt    = (const float*)d_in[4];
    const float* b1    = (const float*)d_in[5];
    const float* W2    = (const float*)d_in[6];
    const float* b2    = (const float*)d_in[7];
    float* out = (float*)d_out;

    k_std<<<BB, 256>>>(cloud);
    k_pack<<<NTOT / 256, 256>>>(cloud, noise);

    // EPS_LIST = np.geomspace(32.0, 0.001**2, 14).astype(np.float32)
    const double blur2 = 0.001 * 0.001;
    const double l0 = log10(32.0);
    const double l1 = log10(blur2);
    const double step = (l1 - l0) / (double)(NITER - 1);
    const double LOG2E = 1.4426950408889634;
    const dim3 gridH(NPT / 32, BB);   // 512 blocks (R9 optimum)
    const dim3 gridA(NPT / 32, BB);

    for (int it = 0; it < NITER; it++) {
        double ev;
        if (it == 0)              ev = 32.0;
        else if (it == NITER - 1) ev = blur2;
        else                      ev = pow(10.0, l0 + (double)it * step);
        const float eps = (float)ev;
        const float ie2 = (float)((double)(1.0f / eps) * LOG2E);
        k_half<0, 0><<<gridH, 256>>>(eps, ie2);              // f-update
        if (it < NITER - 1) k_half<1, 0><<<gridH, 256>>>(eps, ie2);   // g-update
        else                k_half<1, 1><<<gridH, 256>>>(eps, ie2);   // final g-update -> cg
    }

    k_argmin<<<gridA, 256>>>();
    k_mlp<<<NTOT / 256, 256>>>(noise, t, W1, Wt, b1, W2, b2, out);

    (void)in_sizes; (void)n_in; (void)out_size;
}

// round 16
// speedup vs baseline: 1.5154x; 1.0960x over previous
#include <cuda_runtime.h>
#include <math.h>

#define BB  8
#define NPT 2048
#define NTOT (BB*NPT)
#define HID 256
#define NITER 14

typedef unsigned long long u64;

// ---------------- f32x2 packed helpers (sm_103a) ----------------
__device__ __forceinline__ u64 pk2(float lo, float hi) {
    u64 r; asm("mov.b64 %0,{%1,%2};" : "=l"(r) : "f"(lo), "f"(hi)); return r;
}
__device__ __forceinline__ void up2(u64 v, float& lo, float& hi) {
    asm("mov.b64 {%0,%1},%2;" : "=f"(lo), "=f"(hi) : "l"(v));
}
__device__ __forceinline__ u64 fma2_(u64 a, u64 b, u64 c) {
    u64 r; asm("fma.rn.f32x2 %0,%1,%2,%3;" : "=l"(r) : "l"(a), "l"(b), "l"(c)); return r;
}
__device__ __forceinline__ u64 add2_(u64 a, u64 b) {
    u64 r; asm("add.rn.f32x2 %0,%1,%2;" : "=l"(r) : "l"(a), "l"(b)); return r;
}
__device__ __forceinline__ float ex2_(float x) {
    float r; asm("ex2.approx.f32 %0,%1;" : "=f"(r) : "f"(x)); return r;
}

// ---------------- persistent scratch ----------------
__device__ float4 g_xp[NTOT];   // noise points packed: (x,y,z,|x|^2)
__device__ float4 g_yp[NTOT];   // x0 points packed:    (x,y,z,|y|^2)
// interleaved pair tiles for k_half / k_argmin reduce side:
//   g_xy*[pair] = (x_{2j}, x_{2j+1}, y_{2j}, y_{2j+1})
//   g_zc*[pair] = (z_{2j}, z_{2j+1}, c_{2j}, c_{2j+1}),  c = phi - 0.5*|p|^2
//   (after the LAST g-update, the c channel of g_zcY holds cg = 0.5*g - 0.5*|y|^2)
__device__ float4 g_xyX[NTOT/2], g_zcX[NTOT/2];   // X side (noise)
__device__ float4 g_xyY[NTOT/2], g_zcY[NTOT/2];   // Y side (x0)
__device__ float  g_std[BB];
__device__ int    g_idx[NTOT];

// ---------------- per-batch std (ddof=1) ----------------
__global__ void k_std(const float* __restrict__ cloud) {
    __shared__ float red[256];
    const int b = blockIdx.x;
    const float* p = cloud + b * NPT * 3;
    const int tid = threadIdx.x;
    float s = 0.f;
    for (int i = tid; i < NPT * 3; i += 256) s += p[i];
    red[tid] = s; __syncthreads();
    for (int o = 128; o > 0; o >>= 1) { if (tid < o) red[tid] += red[tid + o]; __syncthreads(); }
    const float mean = red[0] / (float)(NPT * 3);
    __syncthreads();
    float s2 = 0.f;
    for (int i = tid; i < NPT * 3; i += 256) { float d = p[i] - mean; s2 = fmaf(d, d, s2); }
    red[tid] = s2; __syncthreads();
    for (int o = 128; o > 0; o >>= 1) { if (tid < o) red[tid] += red[tid + o]; __syncthreads(); }
    if (tid == 0) g_std[b] = sqrtf(red[0] / (float)(NPT * 3 - 1));
}

// ---------------- pack points, build interleaved tiles, init folded constants ----------------
__global__ void k_pack(const float* __restrict__ cloud, const float* __restrict__ noise) {
    int i = blockIdx.x * blockDim.x + threadIdx.x;
    if (i >= NTOT) return;
    int b = i >> 11;
    float sd = g_std[b];
    float c0 = cloud[i * 3 + 0] / sd;
    float c1 = cloud[i * 3 + 1] / sd;
    float c2 = cloud[i * 3 + 2] / sd;
    float yn = __fadd_rn(__fadd_rn(__fmul_rn(c0, c0), __fmul_rn(c1, c1)), __fmul_rn(c2, c2));
    g_yp[i] = make_float4(c0, c1, c2, yn);
    float n0 = noise[i * 3 + 0], n1 = noise[i * 3 + 1], n2 = noise[i * 3 + 2];
    float xn = __fadd_rn(__fadd_rn(__fmul_rn(n0, n0), __fmul_rn(n1, n1)), __fmul_rn(n2, n2));
    g_xp[i] = make_float4(n0, n1, n2, xn);

    const int pr = i >> 1, h = i & 1;
    float* fxyX = (float*)g_xyX; float* fzcX = (float*)g_zcX;
    float* fxyY = (float*)g_xyY; float* fzcY = (float*)g_zcY;
    fxyX[pr * 4 + h]     = n0;
    fxyX[pr * 4 + 2 + h] = n1;
    fzcX[pr * 4 + h]     = n2;
    fzcX[pr * 4 + 2 + h] = __fmul_rn(-0.5f, xn);   // phi==0 -> c = -0.5|x|^2
    fxyY[pr * 4 + h]     = c0;
    fxyY[pr * 4 + 2 + h] = c1;
    fzcY[pr * 4 + h]     = c2;
    fzcY[pr * 4 + 2 + h] = __fmul_rn(-0.5f, yn);
}

// log2(1/2048) is exactly -11
#define LOGC2 (-11.0f)
#define LN2F  (0.6931471805599453f)
#define THR   (-50.0f)   // skip threshold in exp2-arg bits; max-arg >= -41 by duality drift bound

// ---------------- one Sinkhorn half-update: single pass, duality shift, packed accum ----------
// arg(i,j) = (q_i.p_j + c_j)*ie2 + khat_i,  khat_i = c_row_i*ie2. Duality bounds the MAX arg
// (<= ~96 < fp32 overflow 117), so no max pass is needed; tails underflow ex2 to 0 harmlessly.
// SKIP (small-eps launches only): warp-uniform vote — if all 256 (i,j) args of this iteration
// are < THR, their exp contributions are < 2^-9 of S combined (max-arg >= -41) and are dropped.
// DIR==0: rows = noise(x), tile = x0(y) -> writes cX.
// DIR==1: rows = x0(y), tile = noise(x) -> writes cY; if LAST, writes cg = 0.5*g - 0.5*|y|^2.
template <int DIR, int LAST, int SKIP>
__global__ void __launch_bounds__(256, 4) k_half(float eps, float ie2 /* (1/eps)*log2(e) */) {
    __shared__ __align__(16) ulonglong2 sXY[NPT/2], sZC[NPT/2];
    const int b = blockIdx.y;
    const int base = b * NPT;
    const float4* __restrict__ vxy = (DIR ? g_xyX : g_xyY) + (base >> 1);
    const float4* __restrict__ vzc = (DIR ? g_zcX : g_zcY) + (base >> 1);
    const float4* __restrict__ Pq  = DIR ? g_yp : g_xp;
    const float*  __restrict__ rowzc = (const float*)(DIR ? g_zcY : g_zcX);

    const int tid = threadIdx.x;
    {
        float4* dxy = (float4*)sXY; float4* dzc = (float4*)sZC;
#pragma unroll
        for (int j = tid; j < NPT / 2; j += 256) { dxy[j] = vxy[j]; dzc[j] = vzc[j]; }
    }
    __syncthreads();

    const int warp = tid >> 5, lane = tid & 31;
    const int r0 = blockIdx.x * 32 + warp * 4;

    u64 qx2[4], qy2[4], qz2[4], K[4];
    float qw[4], khat[4];
#pragma unroll
    for (int k = 0; k < 4; k++) {
        float4 q = Pq[base + r0 + k];
        qx2[k] = pk2(q.x, q.x);
        qy2[k] = pk2(q.y, q.y);
        qz2[k] = pk2(q.z, q.z);
        qw[k] = q.w;
        float crow = rowzc[(((base + r0) >> 1) + (k >> 1)) * 4 + 2 + (k & 1)];
        khat[k] = __fmul_rn(crow, ie2);
        K[k] = pk2(khat[k], khat[k]);
    }
    const u64 IE2P = pk2(ie2, ie2);

    u64 A0 = 0, A1 = 0, A2 = 0, A3 = 0;   // packed (sum of lo, sum of hi) per row

#pragma unroll 4
    for (int it = 0; it < NPT / 64; ++it) {
        const int jj = lane + it * 32;
        const ulonglong2 pxy = sXY[jj];
        const ulonglong2 pzc = sZC[jj];
        u64 ea0 = fma2_(IE2P, fma2_(qz2[0], pzc.x, fma2_(qy2[0], pxy.y, fma2_(qx2[0], pxy.x, pzc.y))), K[0]);
        u64 ea1 = fma2_(IE2P, fma2_(qz2[1], pzc.x, fma2_(qy2[1], pxy.y, fma2_(qx2[1], pxy.x, pzc.y))), K[1]);
        u64 ea2 = fma2_(IE2P, fma2_(qz2[2], pzc.x, fma2_(qy2[2], pxy.y, fma2_(qx2[2], pxy.x, pzc.y))), K[2]);
        u64 ea3 = fma2_(IE2P, fma2_(qz2[3], pzc.x, fma2_(qy2[3], pxy.y, fma2_(qx2[3], pxy.x, pzc.y))), K[3]);
        float e0l, e0h, e1l, e1h, e2l, e2h, e3l, e3h;
        up2(ea0, e0l, e0h); up2(ea1, e1l, e1h); up2(ea2, e2l, e2h); up2(ea3, e3l, e3h);
        bool fire = true;
        if (SKIP) {
            float m = fmaxf(fmaxf(fmaxf(e0l, e0h), fmaxf(e1l, e1h)),
                            fmaxf(fmaxf(e2l, e2h), fmaxf(e3l, e3h)));
            fire = __any_sync(0xffffffffu, m > THR);
        }
        if (fire) {
            A0 = add2_(A0, pk2(ex2_(e0l), ex2_(e0h)));
            A1 = add2_(A1, pk2(ex2_(e1l), ex2_(e1h)));
            A2 = add2_(A2, pk2(ex2_(e2l), ex2_(e2h)));
            A3 = add2_(A3, pk2(ex2_(e3l), ex2_(e3h)));
        }
    }

    float sw[4];
    {
        float l, h;
        up2(A0, l, h); sw[0] = __fadd_rn(l, h);
        up2(A1, l, h); sw[1] = __fadd_rn(l, h);
        up2(A2, l, h); sw[2] = __fadd_rn(l, h);
        up2(A3, l, h); sw[3] = __fadd_rn(l, h);
    }
#pragma unroll
    for (int k = 0; k < 4; k++) {
        float a = sw[k];
#pragma unroll
        for (int o = 16; o; o >>= 1) a += __shfl_xor_sync(0xffffffffu, a, o);
        sw[k] = a;
    }

    if (lane == 0) {
#pragma unroll
        for (int k = 0; k < 4; k++) {
            // cnew = phi_new - 0.5|q|^2 = -eps*( (LOGC2 - khat)*ln2 + ln S )
            float S = fmaxf(sw[k], 1e-37f);           // guard (unreachable by duality bound)
            float base2 = __fadd_rn(LOGC2, -khat[k]);
            float cnew = __fmul_rn(-eps, fmaf(base2, LN2F, logf(S)));
            const int pr4 = (((base + r0) >> 1) + (k >> 1)) * 4 + 2 + (k & 1);
            if (DIR == 0) {
                ((float*)g_zcX)[pr4] = cnew;                    // f - 0.5|x|^2
            } else if (!LAST) {
                ((float*)g_zcY)[pr4] = cnew;                    // g - 0.5|y|^2
            } else {
                float res = fmaf(0.5f, qw[k], cnew);            // g
                ((float*)g_zcY)[pr4] = fmaf(-0.5f, res, cnew);  // cg = 0.5*g - 0.5*|y|^2
            }
        }
    }
}

// ---------------- folded argmin: argmax_j of u = q.p_j + cg_j (== argmin of sqdist - g) --------
__global__ void __launch_bounds__(256, 4) k_argmin() {
    __shared__ __align__(16) ulonglong2 sXY[NPT/2], sZC[NPT/2];
    const int b = blockIdx.y;
    const int base = b * NPT;
    const int tid = threadIdx.x;
    {
        const float4* vxy = g_xyY + (base >> 1);
        const float4* vzc = g_zcY + (base >> 1);
        float4* dxy = (float4*)sXY; float4* dzc = (float4*)sZC;
#pragma unroll
        for (int j = tid; j < NPT / 2; j += 256) { dxy[j] = vxy[j]; dzc[j] = vzc[j]; }
    }
    __syncthreads();

    const int warp = tid >> 5, lane = tid & 31;
    const int r0 = blockIdx.x * 32 + warp * 4;

    u64 qx2[4], qy2[4], qz2[4];
#pragma unroll
    for (int k = 0; k < 4; k++) {
        float4 q = g_xp[base + r0 + k];
        qx2[k] = pk2(q.x, q.x);
        qy2[k] = pk2(q.y, q.y);
        qz2[k] = pk2(q.z, q.z);
    }
    float bv[4] = {-INFINITY, -INFINITY, -INFINITY, -INFINITY};
    int   bi[4] = {0, 0, 0, 0};

#pragma unroll 4
    for (int it = 0; it < NPT / 64; ++it) {
        const int jj = lane + it * 32;
        const ulonglong2 pxy = sXY[jj];
        const ulonglong2 pzc = sZC[jj];
#pragma unroll
        for (int k = 0; k < 4; k++) {
            u64 u = fma2_(qz2[k], pzc.x, fma2_(qy2[k], pxy.y, fma2_(qx2[k], pxy.x, pzc.y)));
            float ul, uh; up2(u, ul, uh);
            if (ul > bv[k]) { bv[k] = ul; bi[k] = 2 * jj; }
            if (uh > bv[k]) { bv[k] = uh; bi[k] = 2 * jj + 1; }
        }
    }
#pragma unroll
    for (int k = 0; k < 4; k++) {
#pragma unroll
        for (int o = 16; o; o >>= 1) {
            float v2 = __shfl_xor_sync(0xffffffffu, bv[k], o);
            int   i2 = __shfl_xor_sync(0xffffffffu, bi[k], o);
            if (v2 > bv[k] || (v2 == bv[k] && i2 < bi[k])) { bv[k] = v2; bi[k] = i2; }
        }
    }
    if (lane == 0) {
#pragma unroll
        for (int k = 0; k < 4; k++) g_idx[base + r0 + k] = bi[k];
    }
}

// ---------------- gather + MLP head, write (v_pred, v) ----------------
__global__ void __launch_bounds__(256) k_mlp(const float* __restrict__ noise, const float* __restrict__ tt,
                                             const float* __restrict__ W1, const float* __restrict__ Wt,
                                             const float* __restrict__ b1, const float* __restrict__ W2,
                                             const float* __restrict__ b2, float* __restrict__ out) {
    __shared__ float sW1[3 * HID], sW2[HID * 3], sWt[HID], sb1[HID];
    const int tid = threadIdx.x;
    for (int i = tid; i < 3 * HID; i += 256) { sW1[i] = W1[i]; sW2[i] = W2[i]; }
    for (int i = tid; i < HID; i += 256) { sWt[i] = Wt[i]; sb1[i] = b1[i]; }
    __syncthreads();

    const int p = blockIdx.x * 256 + tid;
    const int b = p >> 11;
    const float t = tt[b];
    const int id = g_idx[p];
    const float4 y = g_yp[(b << 11) + id];
    const float n0 = noise[p * 3 + 0], n1 = noise[p * 3 + 1], n2 = noise[p * 3 + 2];
    const float v0 = __fadd_rn(n0, -y.x);
    const float v1 = __fadd_rn(n1, -y.y);
    const float v2 = __fadd_rn(n2, -y.z);
    const float omt = __fadd_rn(1.f, -t);
    const float x0t = __fadd_rn(__fmul_rn(omt, y.x), __fmul_rn(t, n0));
    const float x1t = __fadd_rn(__fmul_rn(omt, y.y), __fmul_rn(t, n1));
    const float x2t = __fadd_rn(__fmul_rn(omt, y.z), __fmul_rn(t, n2));

    float a0 = b2[0], a1 = b2[1], a2 = b2[2];
#pragma unroll 8
    for (int j = 0; j < HID; j++) {
        float h = fmaf(x2t, sW1[2 * HID + j], fmaf(x1t, sW1[HID + j], __fmul_rn(x0t, sW1[j])));
        h = __fadd_rn(__fadd_rn(h, __fmul_rn(t, sWt[j])), sb1[j]);
        h = fmaxf(h, 0.f);
        a0 = fmaf(h, sW2[j * 3 + 0], a0);
        a1 = fmaf(h, sW2[j * 3 + 1], a1);
        a2 = fmaf(h, sW2[j * 3 + 2], a2);
    }
    out[p * 3 + 0] = a0;
    out[p * 3 + 1] = a1;
    out[p * 3 + 2] = a2;
    out[NTOT * 3 + p * 3 + 0] = v0;
    out[NTOT * 3 + p * 3 + 1] = v1;
    out[NTOT * 3 + p * 3 + 2] = v2;
}

// ---------------- launcher ----------------
extern "C" void kernel_launch(void* const* d_in, const int* in_sizes, int n_in,
                              void* d_out, int out_size) {
    const float* cloud = (const float*)d_in[0];
    const float* noise = (const float*)d_in[1];
    const float* t     = (const float*)d_in[2];
    const float* W1    = (const float*)d_in[3];
    const float* Wt    = (const float*)d_in[4];
    const float* b1    = (const float*)d_in[5];
    const float* W2    = (const float*)d_in[6];
    const float* b2    = (const float*)d_in[7];
    float* out = (float*)d_out;

    k_std<<<BB, 256>>>(cloud);
    k_pack<<<NTOT / 256, 256>>>(cloud, noise);

    // EPS_LIST = np.geomspace(32.0, 0.001**2, 14).astype(np.float32)
    const double blur2 = 0.001 * 0.001;
    const double l0 = log10(32.0);
    const double l1 = log10(blur2);
    const double step = (l1 - l0) / (double)(NITER - 1);
    const double LOG2E = 1.4426950408889634;
    const dim3 gridH(NPT / 32, BB);   // 512 blocks (R9/R15 optimum)
    const dim3 gridA(NPT / 32, BB);

    for (int it = 0; it < NITER; it++) {
        double ev;
        if (it == 0)              ev = 32.0;
        else if (it == NITER - 1) ev = blur2;
        else                      ev = pow(10.0, l0 + (double)it * step);
        const float eps = (float)ev;
        const float ie2 = (float)((double)(1.0f / eps) * LOG2E);
        const bool skip = (it >= 8);   // eps <= ~7.8e-4: exp contributions become sparse
        if (!skip) {
            k_half<0, 0, 0><<<gridH, 256>>>(eps, ie2);
            k_half<1, 0, 0><<<gridH, 256>>>(eps, ie2);
        } else if (it < NITER - 1) {
            k_half<0, 0, 1><<<gridH, 256>>>(eps, ie2);
            k_half<1, 0, 1><<<gridH, 256>>>(eps, ie2);
        } else {
            k_half<0, 0, 1><<<gridH, 256>>>(eps, ie2);
            k_half<1, 1, 1><<<gridH, 256>>>(eps, ie2);   // final g-update -> cg
        }
    }

    k_argmin<<<gridA, 256>>>();
    k_mlp<<<NTOT / 256, 256>>>(noise, t, W1, Wt, b1, W2, b2, out);

    (void)in_sizes; (void)n_in; (void)out_size;
}